// round 4
// baseline (speedup 1.0000x reference)
#include <cuda_runtime.h>
#include <cuda_fp16.h>
#include <cstdint>

// Routed capsule layer, B200 (sm_100a).
// x[64,1152,8], W[64,1152,16,8] -> v[64,64,16], 3 routing iterations.
// b_t = (sum_{tau<=t} v_tau) . u  (logits linear in history); iter-1 c == 1/64.
// u cached in fp16, layout [b][i][o][k].

#define NB 64
#define NI 1152
#define KI 8
#define NO 64
#define KO 16

#define K1_IC 16
#define NCH1 (NI / K1_IC)   // 72 i-chunks for k_u partials
#define K2_IC 64
#define NCH2 (NI / K2_IC)   // 18 i-chunks for k_route partials

__device__ __half g_u[(size_t)NB * NI * NO * KO];        // 151 MB
// transposed partials: [b][o][k][chunk], chunk stride 1, row width NCH1
__device__ float g_sp[(size_t)NB * NO * KO * NCH1];      // 18.9 MB
__device__ float g_v1[NB * NO * KO];
__device__ float g_vsum[NB * NO * KO];

// ---------------------------------------------------------------------------
// K1: u = W.x (fp16) + per-chunk partial sums (uniform-c first iteration).
// 8 warps (one o each); lane = ih*16 + k; thread owns W[og][...][k][:] for
// 8 i's in registers (W read from DRAM exactly once). Whole x tile (all 64 b)
// staged once. Stores gathered through smem -> one STG.128 per thread per b.
// grid = (72 i-chunks, 8 o-chunks).
// ---------------------------------------------------------------------------
__global__ void __launch_bounds__(256, 2) k_u(const float* __restrict__ x,
                                              const float* __restrict__ W) {
    __shared__ float sX[NB * K1_IC * KI];            // 32 KB: [b][i_local][j]
    __shared__ __half sG[2][K1_IC * 8 * KO];         // 2 x 4 KB gather tiles

    const int ich = blockIdx.x, och = blockIdx.y;
    const int t = threadIdx.x;
    const int w = t >> 5;                   // local o
    const int l = t & 31;
    const int ih = l >> 4, k = l & 15;
    const int og = och * 8 + w;

    // stage x for ALL batches: 2048 float4, 8 per thread
    {
        const float4* xs = (const float4*)(x + (size_t)ich * K1_IC * KI);
        float4* sx4 = (float4*)sX;
#pragma unroll
        for (int it = 0; it < 8; it++) {
            int idx = t + it * 256;
            int b = idx >> 5, r = idx & 31;
            sx4[idx] = xs[(size_t)b * (NI * KI / 4) + r];
        }
    }

    // register-resident W slice: 8 i x 8 j for this (og, k)
    float4 wr[16];
    {
        const float4* wp = (const float4*)(
            W + ((size_t)(og * NI + ich * K1_IC + ih * 8) * KO + k) * KI);
#pragma unroll
        for (int i = 0; i < 8; i++) {
            wr[2 * i]     = wp[i * 32];
            wr[2 * i + 1] = wp[i * 32 + 1];
        }
    }
    __syncthreads();

    const int grow = t >> 4;          // gather-store row (i_local 0..15)
    const int gcol = t & 15;          // gather-store col (16B unit)

    for (int b = 0; b < NB; b++) {
        __half* gb = sG[b & 1];
        float acc = 0.f;
        const float4* xb = (const float4*)(sX + b * (K1_IC * KI) + ih * 64);
#pragma unroll
        for (int i = 0; i < 8; i++) {
            const float4 x0 = xb[2 * i];
            const float4 x1 = xb[2 * i + 1];
            float v = wr[2*i].x   * x0.x + wr[2*i].y   * x0.y
                    + wr[2*i].z   * x0.z + wr[2*i].w   * x0.w
                    + wr[2*i+1].x * x1.x + wr[2*i+1].y * x1.y
                    + wr[2*i+1].z * x1.z + wr[2*i+1].w * x1.w;
            gb[(ih * 8 + i) * (8 * KO) + w * KO + k] = __float2half(v);
            acc += v;
        }
        acc += __shfl_xor_sync(0xffffffffu, acc, 16);   // join the two i-halves
        if (l < 16)   // transposed partial: [b][og][k=l][ich]
            g_sp[((size_t)(b * NO + og) * KO + l) * NCH1 + ich] = acc;
        __syncthreads();   // gather tile complete
        // one 16B store per thread: rows = i_local, 256B per (i, 8-o block)
        uint4 val = ((const uint4*)gb)[t];
        ((uint4*)(g_u + (size_t)(b * NI + ich * K1_IC + grow) * (NO * KO)
                      + och * 128))[gcol] = val;
        // next iteration writes the other sG buffer: no barrier needed here
    }
}

// fp16x8 unpack from a uint4
__device__ __forceinline__ void unpack8(uint4 r, float* f) {
    union { uint4 u; __half2 h[4]; } cv;
    cv.u = r;
#pragma unroll
    for (int q = 0; q < 4; q++) {
        float2 t = __half22float2(cv.h[q]);
        f[2 * q] = t.x;
        f[2 * q + 1] = t.y;
    }
}

// ---------------------------------------------------------------------------
// K2/K3: routing pass. Warp handles one (b,i) at a time: lane l owns the
// kh=(l&1) half (8 k's) of o in {l>>1, 16+(l>>1), 32+(l>>1), 48+(l>>1)}:
// four perfectly-coalesced uint4 loads per iteration (2KB/warp contiguous).
// rev=1 mirrors the traversal (b and ich) so pass 3 starts where pass 2's
// stream ended -> L2 reuse (u = 151MB vs 126MB L2).
// grid = (18 i-chunks, 64 b), 256 threads (8 warps x 8 i each).
// ---------------------------------------------------------------------------
__global__ void __launch_bounds__(256, 2) k_route(int use_vsum, int rev) {
    const float* __restrict__ vin = use_vsum ? g_vsum : g_v1;
    __shared__ float sRed[8 * NO * KO];     // 32 KB per-warp partials

    const int ich = rev ? (NCH2 - 1 - blockIdx.x) : blockIdx.x;
    const int b   = rev ? (NB - 1 - blockIdx.y)   : blockIdx.y;
    const int t = threadIdx.x, w = t >> 5, l = t & 31;
    const int o0 = l >> 1, kh = l & 1;

    // v slices for this lane's 4 capsules (8 floats each)
    float v[4][8];
#pragma unroll
    for (int m = 0; m < 4; m++) {
        const float4* p = (const float4*)(vin + ((size_t)b * NO + (m * 16 + o0)) * KO + kh * 8);
        float4 a = p[0], c = p[1];
        v[m][0]=a.x; v[m][1]=a.y; v[m][2]=a.z; v[m][3]=a.w;
        v[m][4]=c.x; v[m][5]=c.y; v[m][6]=c.z; v[m][7]=c.w;
    }
    float acc[4][8];
#pragma unroll
    for (int m = 0; m < 4; m++)
#pragma unroll
        for (int q = 0; q < 8; q++) acc[m][q] = 0.f;

    for (int it = 0; it < 8; it++) {
        const int ig = ich * K2_IC + w * 8 + it;
        const uint4* up = (const uint4*)(g_u + (size_t)(b * NI + ig) * (NO * KO));
        uint4 R0 = up[l];
        uint4 R1 = up[l + 32];
        uint4 R2 = up[l + 64];
        uint4 R3 = up[l + 96];
        float u[4][8];
        unpack8(R0, u[0]); unpack8(R1, u[1]); unpack8(R2, u[2]); unpack8(R3, u[3]);

        float L[4];
#pragma unroll
        for (int m = 0; m < 4; m++) {
            float p = 0.f;
#pragma unroll
            for (int q = 0; q < 8; q++) p += v[m][q] * u[m][q];
            L[m] = p + __shfl_xor_sync(0xffffffffu, p, 1);   // full 16-k dot
        }
        float mx = fmaxf(fmaxf(L[0], L[1]), fmaxf(L[2], L[3]));
#pragma unroll
        for (int d = 2; d <= 16; d <<= 1)
            mx = fmaxf(mx, __shfl_xor_sync(0xffffffffu, mx, d));
        float e[4];
        float sm = 0.f;
#pragma unroll
        for (int m = 0; m < 4; m++) { e[m] = __expf(L[m] - mx); sm += e[m]; }
#pragma unroll
        for (int d = 2; d <= 16; d <<= 1)
            sm += __shfl_xor_sync(0xffffffffu, sm, d);
        const float inv = __fdividef(1.f, sm);
#pragma unroll
        for (int m = 0; m < 4; m++) {
            const float c = e[m] * inv;
#pragma unroll
            for (int q = 0; q < 8; q++) acc[m][q] += c * u[m][q];
        }
    }

    // per-warp partials -> smem; element index for (m,lane) is 256*m + 8*l + q
    float4* sr4 = (float4*)sRed;
#pragma unroll
    for (int m = 0; m < 4; m++) {
        sr4[w * 256 + m * 64 + 2 * l]     = make_float4(acc[m][0], acc[m][1], acc[m][2], acc[m][3]);
        sr4[w * 256 + m * 64 + 2 * l + 1] = make_float4(acc[m][4], acc[m][5], acc[m][6], acc[m][7]);
    }
    __syncthreads();
    float4 r = sr4[t];
#pragma unroll
    for (int ww = 1; ww < 8; ww++) {
        float4 p = sr4[ww * 256 + t];
        r.x += p.x; r.y += p.y; r.z += p.z; r.w += p.w;
    }
    // transposed partial write: element e = 4t+q -> row b*1024+e, col ich
    {
        const size_t row0 = (size_t)b * (NO * KO) + 4 * t;
        g_sp[(row0 + 0) * NCH1 + ich] = r.x;
        g_sp[(row0 + 1) * NCH1 + ich] = r.y;
        g_sp[(row0 + 2) * NCH1 + ich] = r.z;
        g_sp[(row0 + 3) * NCH1 + ich] = r.w;
    }
}

// ---------------------------------------------------------------------------
// Reduce chunk partials -> s, squash, write v. One thread per (b,o,k) element
// (65536 threads); per-thread chunk walk is now CONTIGUOUS (stride-1 floats).
// mode 0: v1 = squash(s/64); mode 1: vsum = v1 + squash(s); mode 2: out.
// ---------------------------------------------------------------------------
__global__ void __launch_bounds__(256) k_reduce(int nch, float scale, int mode,
                                                float* __restrict__ dout) {
    const int tg = blockIdx.x * 256 + threadIdx.x;   // b*1024 + o*16 + k
    const float* p = g_sp + (size_t)tg * NCH1;
    float s = 0.f;
    if (nch == NCH1) {
        const float4* p4 = (const float4*)p;
        float4 a0 = make_float4(0.f, 0.f, 0.f, 0.f);
#pragma unroll
        for (int c = 0; c < NCH1 / 4; c++) {
            float4 a = p4[c];
            a0.x += a.x; a0.y += a.y; a0.z += a.z; a0.w += a.w;
        }
        s = (a0.x + a0.y) + (a0.z + a0.w);
    } else {
        const float4* p4 = (const float4*)p;
        float4 a0 = make_float4(0.f, 0.f, 0.f, 0.f);
#pragma unroll
        for (int c = 0; c < NCH2 / 4; c++) {   // 4 float4 = 16
            float4 a = p4[c];
            a0.x += a.x; a0.y += a.y; a0.z += a.z; a0.w += a.w;
        }
        s = (a0.x + a0.y) + (a0.z + a0.w) + p[16] + p[17];
    }
    s *= scale;
    float n2 = s * s;
#pragma unroll
    for (int d = 1; d <= 8; d <<= 1)
        n2 += __shfl_xor_sync(0xffffffffu, n2, d);   // stays within k-group
    const float scl = n2 / (1.f + n2) * rsqrtf(n2 + 1e-7f);
    const float val = s * scl;
    if (mode == 0)      g_v1[tg] = val;
    else if (mode == 1) g_vsum[tg] = val + g_v1[tg];
    else                dout[tg] = val;
}

// ---------------------------------------------------------------------------
extern "C" void kernel_launch(void* const* d_in, const int* in_sizes, int n_in,
                              void* d_out, int out_size) {
    const float* x = (const float*)d_in[0];
    const float* W = (const float*)d_in[1];
    if (in_sizes[0] != NB * NI * KI) {
        x = (const float*)d_in[1];
        W = (const float*)d_in[0];
    }
    float* out = (float*)d_out;

    k_u<<<dim3(NCH1, NO / 8), 256>>>(x, W);                 // u + s1 partials
    k_reduce<<<256, 256>>>(NCH1, 1.f / 64.f, 0, nullptr);   // v1
    k_route<<<dim3(NCH2, NB), 256>>>(0, 0);                 // s2 (forward)
    k_reduce<<<256, 256>>>(NCH2, 1.f, 1, nullptr);          // v2, vsum
    k_route<<<dim3(NCH2, NB), 256>>>(1, 1);                 // s3 (reversed: L2 reuse)
    k_reduce<<<256, 256>>>(NCH2, 1.f, 2, out);              // v3 -> out
}

// round 5
// speedup vs baseline: 1.0814x; 1.0814x over previous
#include <cuda_runtime.h>
#include <cuda_fp16.h>
#include <cstdint>

// Routed capsule layer, B200 (sm_100a).
// x[64,1152,8], W[64,1152,16,8] -> v[64,64,16], 3 routing iterations.
// b_t = (sum_{tau<=t} v_tau) . u  (logits linear in history); iter-1 c == 1/64.
// u cached in fp16, layout [b][i][o][k].

#define NB 64
#define NI 1152
#define KI 8
#define NO 64
#define KO 16

#define K1_IC 16
#define NCH1 (NI / K1_IC)   // 72 i-chunks for k_u partials
#define K2_IC 64
#define NCH2 (NI / K2_IC)   // 18 i-chunks for k_route partials

__device__ __half g_u[(size_t)NB * NI * NO * KO];        // 151 MB
// chunk-major partials: [chunk][b][o][k] -> coalesced writes AND reads
__device__ float g_sp[(size_t)NCH1 * NB * NO * KO];      // 18.9 MB
__device__ float g_v1[NB * NO * KO];
__device__ float g_vsum[NB * NO * KO];

// ---------------------------------------------------------------------------
// K1: u = W.x (fp16) + per-chunk partial sums (uniform-c first iteration).
// 8 warps (one o each); lane = ih*16 + k; W slice in registers (read once).
// Whole x tile (all 64 b) staged once; stores gathered through smem ->
// one STG.128 per thread per b. grid = (72 i-chunks, 8 o-chunks).
// ---------------------------------------------------------------------------
__global__ void __launch_bounds__(256, 2) k_u(const float* __restrict__ x,
                                              const float* __restrict__ W) {
    __shared__ float sX[NB * K1_IC * KI];            // 32 KB: [b][i_local][j]
    __shared__ __half sG[2][K1_IC * 8 * KO];         // 2 x 4 KB gather tiles

    const int ich = blockIdx.x, och = blockIdx.y;
    const int t = threadIdx.x;
    const int w = t >> 5;                   // local o
    const int l = t & 31;
    const int ih = l >> 4, k = l & 15;
    const int og = och * 8 + w;

    {   // stage x for ALL batches: 2048 float4, 8 per thread
        const float4* xs = (const float4*)(x + (size_t)ich * K1_IC * KI);
        float4* sx4 = (float4*)sX;
#pragma unroll
        for (int it = 0; it < 8; it++) {
            int idx = t + it * 256;
            int b = idx >> 5, r = idx & 31;
            sx4[idx] = xs[(size_t)b * (NI * KI / 4) + r];
        }
    }

    // register-resident W slice: 8 i x 8 j for this (og, k)
    float4 wr[16];
    {
        const float4* wp = (const float4*)(
            W + ((size_t)(og * NI + ich * K1_IC + ih * 8) * KO + k) * KI);
#pragma unroll
        for (int i = 0; i < 8; i++) {
            wr[2 * i]     = wp[i * 32];
            wr[2 * i + 1] = wp[i * 32 + 1];
        }
    }
    __syncthreads();

    const int grow = t >> 4;          // gather-store row (i_local 0..15)
    const int gcol = t & 15;          // gather-store col (16B unit)

    for (int b = 0; b < NB; b++) {
        __half* gb = sG[b & 1];
        float acc = 0.f;
        const float4* xb = (const float4*)(sX + b * (K1_IC * KI) + ih * 64);
#pragma unroll
        for (int i = 0; i < 8; i++) {
            const float4 x0 = xb[2 * i];
            const float4 x1 = xb[2 * i + 1];
            float v = wr[2*i].x   * x0.x + wr[2*i].y   * x0.y
                    + wr[2*i].z   * x0.z + wr[2*i].w   * x0.w
                    + wr[2*i+1].x * x1.x + wr[2*i+1].y * x1.y
                    + wr[2*i+1].z * x1.z + wr[2*i+1].w * x1.w;
            gb[(ih * 8 + i) * (8 * KO) + w * KO + k] = __float2half(v);
            acc += v;
        }
        acc += __shfl_xor_sync(0xffffffffu, acc, 16);   // join the two i-halves
        if (l < 16)   // chunk-major partial: [ich][b][og][k] (coalesced)
            g_sp[(size_t)(ich * NB + b) * (NO * KO) + og * KO + l] = acc;
        __syncthreads();   // gather tile complete
        uint4 val = ((const uint4*)gb)[t];
        ((uint4*)(g_u + (size_t)(b * NI + ich * K1_IC + grow) * (NO * KO)
                      + och * 128))[gcol] = val;
        // next iteration writes the other sG buffer: no barrier needed here
    }
}

// ---------------------------------------------------------------------------
// transient-unpack helpers: consume packed fp16x8 without materializing floats
// ---------------------------------------------------------------------------
__device__ __forceinline__ float dot8(uint4 r, const float* v) {
    float p = 0.f; float2 f;
    f = __half22float2(*(const __half2*)&r.x); p += v[0]*f.x + v[1]*f.y;
    f = __half22float2(*(const __half2*)&r.y); p += v[2]*f.x + v[3]*f.y;
    f = __half22float2(*(const __half2*)&r.z); p += v[4]*f.x + v[5]*f.y;
    f = __half22float2(*(const __half2*)&r.w); p += v[6]*f.x + v[7]*f.y;
    return p;
}
__device__ __forceinline__ void fma8(uint4 r, float c, float* a) {
    float2 f;
    f = __half22float2(*(const __half2*)&r.x); a[0] += c*f.x; a[1] += c*f.y;
    f = __half22float2(*(const __half2*)&r.y); a[2] += c*f.x; a[3] += c*f.y;
    f = __half22float2(*(const __half2*)&r.z); a[4] += c*f.x; a[5] += c*f.y;
    f = __half22float2(*(const __half2*)&r.w); a[6] += c*f.x; a[7] += c*f.y;
}

// ---------------------------------------------------------------------------
// K2/K3: routing pass. Warp handles one (b,i) per iteration: lane l owns the
// kh=(l&1) half (8 k's) of o in {l>>1, 16+(l>>1), 32+(l>>1), 48+(l>>1)}:
// four perfectly-coalesced uint4 loads per iter (2KB/warp). u stays PACKED in
// registers (unpacked transiently in dot/fma) and the next iteration's loads
// are prefetched -> 8 outstanding 128B loads per warp (2x MLP, DRAM-saturating
// at 2 blocks/SM). grid = (18 i-chunks, 64 b), 256 threads (8 warps x 8 i).
// ---------------------------------------------------------------------------
__global__ void __launch_bounds__(256, 2) k_route(int use_vsum) {
    const float* __restrict__ vin = use_vsum ? g_vsum : g_v1;
    __shared__ float sRed[8 * NO * KO];     // 32 KB per-warp partials

    const int ich = blockIdx.x, b = blockIdx.y;
    const int t = threadIdx.x, w = t >> 5, l = t & 31;
    const int o0 = l >> 1, kh = l & 1;

    // v slices for this lane's 4 capsules (8 floats each)
    float v[4][8];
#pragma unroll
    for (int m = 0; m < 4; m++) {
        const float4* p = (const float4*)(vin + ((size_t)b * NO + (m * 16 + o0)) * KO + kh * 8);
        float4 a = p[0], c = p[1];
        v[m][0]=a.x; v[m][1]=a.y; v[m][2]=a.z; v[m][3]=a.w;
        v[m][4]=c.x; v[m][5]=c.y; v[m][6]=c.z; v[m][7]=c.w;
    }
    float acc[4][8];
#pragma unroll
    for (int m = 0; m < 4; m++)
#pragma unroll
        for (int q = 0; q < 8; q++) acc[m][q] = 0.f;

    // base for this warp's 8 i's; each i-row is 128 uint4
    const uint4* ub = (const uint4*)(g_u + (size_t)(b * NI + ich * K2_IC + w * 8) * (NO * KO));
    uint4 P0 = ub[l], P1 = ub[l + 32], P2 = ub[l + 64], P3 = ub[l + 96];

#pragma unroll
    for (int it = 0; it < 8; it++) {
        uint4 C0 = P0, C1 = P1, C2 = P2, C3 = P3;
        if (it < 7) {
            const uint4* un = ub + (it + 1) * 128;
            P0 = un[l]; P1 = un[l + 32]; P2 = un[l + 64]; P3 = un[l + 96];
        }
        float L[4];
        L[0] = dot8(C0, v[0]); L[1] = dot8(C1, v[1]);
        L[2] = dot8(C2, v[2]); L[3] = dot8(C3, v[3]);
#pragma unroll
        for (int m = 0; m < 4; m++)
            L[m] += __shfl_xor_sync(0xffffffffu, L[m], 1);   // full 16-k dot

        float mx = fmaxf(fmaxf(L[0], L[1]), fmaxf(L[2], L[3]));
#pragma unroll
        for (int d = 2; d <= 16; d <<= 1)
            mx = fmaxf(mx, __shfl_xor_sync(0xffffffffu, mx, d));
        float e0 = __expf(L[0] - mx), e1 = __expf(L[1] - mx);
        float e2 = __expf(L[2] - mx), e3 = __expf(L[3] - mx);
        float sm = (e0 + e1) + (e2 + e3);
#pragma unroll
        for (int d = 2; d <= 16; d <<= 1)
            sm += __shfl_xor_sync(0xffffffffu, sm, d);
        const float inv = __fdividef(1.f, sm);
        fma8(C0, e0 * inv, acc[0]); fma8(C1, e1 * inv, acc[1]);
        fma8(C2, e2 * inv, acc[2]); fma8(C3, e3 * inv, acc[3]);
    }

    // per-warp partials -> smem; element index for (m,lane) is 256*m + 8*l + q
    float4* sr4 = (float4*)sRed;
#pragma unroll
    for (int m = 0; m < 4; m++) {
        sr4[w * 256 + m * 64 + 2 * l]     = make_float4(acc[m][0], acc[m][1], acc[m][2], acc[m][3]);
        sr4[w * 256 + m * 64 + 2 * l + 1] = make_float4(acc[m][4], acc[m][5], acc[m][6], acc[m][7]);
    }
    __syncthreads();
    float4 r = sr4[t];
#pragma unroll
    for (int ww = 1; ww < 8; ww++) {
        float4 p = sr4[ww * 256 + t];
        r.x += p.x; r.y += p.y; r.z += p.z; r.w += p.w;
    }
    ((float4*)(g_sp + (size_t)(ich * NB + b) * (NO * KO)))[t] = r;   // coalesced
}

// ---------------------------------------------------------------------------
// Reduce chunk partials -> s, squash, write v. One thread per (b,o,k) element;
// chunk-major layout -> loads coalesced across threads at every chunk step.
// mode 0: v1 = squash(s/64); mode 1: vsum = v1 + squash(s); mode 2: out.
// ---------------------------------------------------------------------------
__global__ void __launch_bounds__(256) k_reduce(int nch, float scale, int mode,
                                                float* __restrict__ dout) {
    const int tg = blockIdx.x * 256 + threadIdx.x;   // b*1024 + o*16 + k
    const float* p = g_sp + tg;
    float s = 0.f;
#pragma unroll 6
    for (int c = 0; c < nch; c++) s += p[(size_t)c * (NB * NO * KO)];
    s *= scale;
    float n2 = s * s;
#pragma unroll
    for (int d = 1; d <= 8; d <<= 1)
        n2 += __shfl_xor_sync(0xffffffffu, n2, d);   // stays within k-group
    const float scl = n2 / (1.f + n2) * rsqrtf(n2 + 1e-7f);
    const float val = s * scl;
    if (mode == 0)      g_v1[tg] = val;
    else if (mode == 1) g_vsum[tg] = val + g_v1[tg];
    else                dout[tg] = val;
}

// ---------------------------------------------------------------------------
extern "C" void kernel_launch(void* const* d_in, const int* in_sizes, int n_in,
                              void* d_out, int out_size) {
    const float* x = (const float*)d_in[0];
    const float* W = (const float*)d_in[1];
    if (in_sizes[0] != NB * NI * KI) {
        x = (const float*)d_in[1];
        W = (const float*)d_in[0];
    }
    float* out = (float*)d_out;

    k_u<<<dim3(NCH1, NO / 8), 256>>>(x, W);                 // u + s1 partials
    k_reduce<<<256, 256>>>(NCH1, 1.f / 64.f, 0, nullptr);   // v1
    k_route<<<dim3(NCH2, NB), 256>>>(0);                    // s2
    k_reduce<<<256, 256>>>(NCH2, 1.f, 1, nullptr);          // v2, vsum
    k_route<<<dim3(NCH2, NB), 256>>>(1);                    // s3
    k_reduce<<<256, 256>>>(NCH2, 1.f, 2, out);              // v3 -> out
}